// round 17
// baseline (speedup 1.0000x reference)
#include <cuda_runtime.h>
#include <math.h>

// Problem constants
#define NN_ 4096
#define DD_ 1024
#define HH_ 8
#define DH_ 128
#define FF_ 2048   // 2*D
#define D3_ 3072   // 3*D (fused QKV width)

static const size_t SZ_ND = (size_t)NN_ * DD_;      // 4,194,304

// Scratch layout (floats):
//  QKV : 3*SZ_ND | AO,P,Hb,Fb : 4*SZ_ND | T : 2*SZ_ND | x_tf : 1*SZ_ND
//  W3_tf : 3M | Wo_tf : 1M | W1_tf : 2M | W2_tf : 2M
__device__ float g_scratch[12 * 4194304ull];

// ---------------------------------------------------------------------------
// TF32 + cp.async helpers
// ---------------------------------------------------------------------------
__device__ __forceinline__ unsigned f2tf(float f) {
    unsigned u;
    asm("cvt.rna.tf32.f32 %0, %1;" : "=r"(u) : "f"(f));
    return u;
}

__device__ __forceinline__ void mma_tf32(float* d, const unsigned* a, const unsigned* b) {
    asm volatile(
        "mma.sync.aligned.m16n8k8.row.col.f32.tf32.tf32.f32 "
        "{%0,%1,%2,%3}, {%4,%5,%6,%7}, {%8,%9}, {%0,%1,%2,%3};"
        : "+f"(d[0]), "+f"(d[1]), "+f"(d[2]), "+f"(d[3])
        : "r"(a[0]), "r"(a[1]), "r"(a[2]), "r"(a[3]), "r"(b[0]), "r"(b[1]));
}

__device__ __forceinline__ unsigned sm_u32(const void* p) {
    return (unsigned)__cvta_generic_to_shared(p);
}
#define CPA16(s, g) asm volatile("cp.async.cg.shared.global [%0], [%1], 16;" :: "r"(s), "l"(g))
#define CPCOMMIT()  asm volatile("cp.async.commit_group;")
#define CPWAIT(n)   asm volatile("cp.async.wait_group %0;" :: "n"(n))

// ---------------------------------------------------------------------------
// Round to tf32: contiguous, and strided-concat (for packing Wq|Wk|Wv).
// ---------------------------------------------------------------------------
__global__ void __launch_bounds__(256) round_tf_k(
    const float* __restrict__ in, float* __restrict__ out, int n4)
{
    int i = blockIdx.x * 256 + threadIdx.x;
    if (i < n4) {
        float4 v = ((const float4*)in)[i];
        v.x = __uint_as_float(f2tf(v.x));
        v.y = __uint_as_float(f2tf(v.y));
        v.z = __uint_as_float(f2tf(v.z));
        v.w = __uint_as_float(f2tf(v.w));
        ((float4*)out)[i] = v;
    }
}

__global__ void __launch_bounds__(256) round_tf_cat_k(
    const float* __restrict__ in, float* __restrict__ out,
    int cols4, int out_ld4, int col_off4, int n4)
{
    int i = blockIdx.x * 256 + threadIdx.x;
    if (i < n4) {
        int row = i / cols4;
        int c4  = i - row * cols4;
        float4 v = ((const float4*)in)[i];
        v.x = __uint_as_float(f2tf(v.x));
        v.y = __uint_as_float(f2tf(v.y));
        v.z = __uint_as_float(f2tf(v.z));
        v.w = __uint_as_float(f2tf(v.w));
        ((float4*)out)[(size_t)row * out_ld4 + col_off4 + c4] = v;
    }
}

// ---------------------------------------------------------------------------
// TF32 GEMM v3: 128x128 CTA tile, 4 warps, 64x64 warp tile (LDS/MMA = 1.0).
// BK=32, 2-stage cp.async, operands pre-rounded tf32.
// EPI: 0 none, 1 +bias, 2 gelu(+bias), 3 +bias+addm
// ---------------------------------------------------------------------------
#define BM 128
#define BN 128
#define GBK 32
#define GTH 128
#define A_LD 36
#define B_LD 136
#define A_SZ (BM * A_LD)
#define B_SZ (GBK * B_LD)

template <int EPI, bool TFOUT>
__global__ void __launch_bounds__(GTH, 2) gemm_tc(
    const float* __restrict__ A, const float* __restrict__ B, float* __restrict__ C,
    int K, int lda, int ldb, int ldc,
    const float* __restrict__ bias,
    const float* __restrict__ addm, int ldadd)
{
    extern __shared__ float smg[];
    float* As = smg;               // 2 stages x 128x36
    float* Bs = smg + 2 * A_SZ;    // 2 stages x 32x136

    const int tid  = threadIdx.x;
    const int lane = tid & 31;
    const int wid  = tid >> 5;          // 0..3
    const int gid  = lane >> 2;
    const int tq   = lane & 3;
    const int wm0  = (wid & 1) * 64;
    const int wn0  = (wid >> 1) * 64;
    const int row0 = blockIdx.y * BM;
    const int col0 = blockIdx.x * BN;

    auto issue = [&](int st, int k0) {
        float* ad = As + st * A_SZ;
        float* bd = Bs + st * B_SZ;
#pragma unroll
        for (int i = 0; i < 8; i++) {
            int c = tid + i * GTH;
            int row = c >> 3, ko = (c & 7) * 4;
            CPA16(sm_u32(ad + row * A_LD + ko), A + (size_t)(row0 + row) * lda + k0 + ko);
        }
#pragma unroll
        for (int i = 0; i < 8; i++) {
            int c = tid + i * GTH;
            int row = c >> 5, no = (c & 31) * 4;
            CPA16(sm_u32(bd + row * B_LD + no), B + (size_t)(k0 + row) * ldb + col0 + no);
        }
        CPCOMMIT();
    };

    float acc[4][8][4];
#pragma unroll
    for (int mt = 0; mt < 4; mt++)
#pragma unroll
        for (int nt = 0; nt < 8; nt++)
#pragma unroll
            for (int c = 0; c < 4; c++) acc[mt][nt][c] = 0.f;

    const int KT = K / GBK;
    issue(0, 0);

    for (int it = 0; it < KT; it++) {
        if (it + 1 < KT) { issue((it + 1) & 1, (it + 1) * GBK); CPWAIT(1); }
        else             { CPWAIT(0); }
        __syncthreads();

        const float* Ab = As + (it & 1) * A_SZ;
        const float* Bb = Bs + (it & 1) * B_SZ;
#pragma unroll
        for (int ks = 0; ks < 4; ks++) {
            const int k8 = ks * 8;
            unsigned af[4][4], bf[8][2];
#pragma unroll
            for (int mt = 0; mt < 4; mt++) {
                const int m = wm0 + mt * 16 + gid;
                af[mt][0] = __float_as_uint(Ab[(m) * A_LD + k8 + tq]);
                af[mt][1] = __float_as_uint(Ab[(m + 8) * A_LD + k8 + tq]);
                af[mt][2] = __float_as_uint(Ab[(m) * A_LD + k8 + tq + 4]);
                af[mt][3] = __float_as_uint(Ab[(m + 8) * A_LD + k8 + tq + 4]);
            }
#pragma unroll
            for (int nt = 0; nt < 8; nt++) {
                const int n = wn0 + nt * 8 + gid;
                bf[nt][0] = __float_as_uint(Bb[(k8 + tq) * B_LD + n]);
                bf[nt][1] = __float_as_uint(Bb[(k8 + tq + 4) * B_LD + n]);
            }
#pragma unroll
            for (int mt = 0; mt < 4; mt++)
#pragma unroll
                for (int nt = 0; nt < 8; nt++)
                    mma_tf32(acc[mt][nt], af[mt], bf[nt]);
        }
        __syncthreads();
    }

    // -------- epilogue --------
#pragma unroll
    for (int mt = 0; mt < 4; mt++) {
        const int r = row0 + wm0 + mt * 16 + gid;
#pragma unroll
        for (int nt = 0; nt < 8; nt++) {
            const int c = col0 + wn0 + nt * 8 + 2 * tq;
            float v0 = acc[mt][nt][0];
            float v1 = acc[mt][nt][1];
            float v2 = acc[mt][nt][2];
            float v3 = acc[mt][nt][3];
            if (EPI == 1) {
                v0 += bias[c]; v1 += bias[c + 1];
                v2 += bias[c]; v3 += bias[c + 1];
            } else if (EPI == 2) {
                v0 += bias[c]; v1 += bias[c + 1];
                v2 += bias[c]; v3 += bias[c + 1];
                v0 = 0.5f * v0 * (1.f + erff(v0 * 0.70710678118654752f));
                v1 = 0.5f * v1 * (1.f + erff(v1 * 0.70710678118654752f));
                v2 = 0.5f * v2 * (1.f + erff(v2 * 0.70710678118654752f));
                v3 = 0.5f * v3 * (1.f + erff(v3 * 0.70710678118654752f));
            } else if (EPI == 3) {
                float2 m0 = *(const float2*)&addm[(size_t)r * ldadd + c];
                float2 m1 = *(const float2*)&addm[(size_t)(r + 8) * ldadd + c];
                v0 += bias[c] + m0.x;     v1 += bias[c + 1] + m0.y;
                v2 += bias[c] + m1.x;     v3 += bias[c + 1] + m1.y;
            }
            if (TFOUT) {
                v0 = __uint_as_float(f2tf(v0));
                v1 = __uint_as_float(f2tf(v1));
                v2 = __uint_as_float(f2tf(v2));
                v3 = __uint_as_float(f2tf(v3));
            }
            *(float2*)&C[(size_t)r * ldc + c] = make_float2(v0, v1);
            *(float2*)&C[(size_t)(r + 8) * ldc + c] = make_float2(v2, v3);
        }
    }
}

// ---------------------------------------------------------------------------
// Flash attention v6: QROWS=256, 8 warps, each warp 32 q-rows (2 row-tiles);
// K/V fragments reused across both row-tiles (LDS/MMA 2.5 -> 1.5).
// KTILE=32, 2-stage cp.async, Q/K/V pre-rounded tf32 (stride ldk=3072).
// smem: Qs 256x132 | K 2x32x132 | V 2x32x136 = 203,776 B (1 CTA/SM).
// ---------------------------------------------------------------------------
#define QROWS 256
#define KTILE 32
#define FTH 256
#define Q_LDS 132
#define K_LDS 132
#define V_LDS 136
#define Q_SZ (QROWS * Q_LDS)
#define K_SZ (KTILE * K_LDS)
#define V_SZ (KTILE * V_LDS)

__global__ void __launch_bounds__(FTH, 1) flash_attn(
    const float* __restrict__ Qm, const float* __restrict__ Km,
    const float* __restrict__ Vm, int ldk,
    const float* __restrict__ adj,
    const float* __restrict__ adj_bias, float* __restrict__ AO, float scale)
{
    extern __shared__ float sm[];
    float* Qs  = sm;                       // 256 x 132 [row][dh]
    float* Kst = sm + Q_SZ;                // 2 x 32x132 [key][dh]
    float* Vst = Kst + 2 * K_SZ;           // 2 x 32x136 [key][dh]

    const int h  = blockIdx.x;
    const int q0 = blockIdx.y * QROWS;
    const int tid  = threadIdx.x;
    const int lane = tid & 31;
    const int wid  = tid >> 5;             // 0..7
    const int gid  = lane >> 2;
    const int tq   = lane & 3;
    const int wr0  = wid * 32;             // warp's q-row base (32 rows/warp)

    const float beta = adj_bias[h];

    // ---- Q tile: 256 rows x 128 floats, one cp.async group ----
    {
        const float* qb = Qm + (size_t)q0 * ldk + h * DH_;
#pragma unroll
        for (int i = 0; i < 32; i++) {
            int c = tid + i * FTH;
            int row = c >> 5, off = (c & 31) * 4;
            CPA16(sm_u32(Qs + row * Q_LDS + off), qb + (size_t)row * ldk + off);
        }
        CPCOMMIT();
    }

    auto issue = [&](int st, int j) {
        const float* kb = Km + (size_t)(j * KTILE) * ldk + h * DH_;
        const float* vb = Vm + (size_t)(j * KTILE) * ldk + h * DH_;
        float* kd = Kst + st * K_SZ;
        float* vd = Vst + st * V_SZ;
#pragma unroll
        for (int i = 0; i < 4; i++) {
            int c = tid + i * FTH;
            int row = c >> 5, off = (c & 31) * 4;
            CPA16(sm_u32(kd + row * K_LDS + off), kb + (size_t)row * ldk + off);
            CPA16(sm_u32(vd + row * V_LDS + off), vb + (size_t)row * ldk + off);
        }
        CPCOMMIT();
    };

    // o[rt][nt][4] : rows wr0+rt*16+{gid,gid+8}, dh cols nt*8+2tq(+1)
    float o[2][16][4];
#pragma unroll
    for (int rt = 0; rt < 2; rt++)
#pragma unroll
        for (int nt = 0; nt < 16; nt++)
#pragma unroll
            for (int c = 0; c < 4; c++) o[rt][nt][c] = 0.f;
    // softmax state per row-group g (g = rt*2 + half): rows wr0 + g*8 + gid
    float mR[4] = {-1e30f, -1e30f, -1e30f, -1e30f};
    float lR[4] = {0.f, 0.f, 0.f, 0.f};

    const int NT = NN_ / KTILE;
    issue(0, 0);

    const float* arow[4];
#pragma unroll
    for (int g = 0; g < 4; g++)
        arow[g] = adj + (size_t)(q0 + wr0 + g * 8 + gid) * NN_;

    for (int j = 0; j < NT; j++) {
        if (j + 1 < NT) { issue((j + 1) & 1, j + 1); CPWAIT(1); }
        else            { CPWAIT(0); }
        __syncthreads();

        // ---- hoisted adj loads (in flight during QK MMA block) ----
        const int kj0 = j * KTILE;
        float2 aj[4][4];
#pragma unroll
        for (int g = 0; g < 4; g++)
#pragma unroll
            for (int nt = 0; nt < 4; nt++)
                aj[g][nt] = *(const float2*)(arow[g] + kj0 + nt * 8 + 2 * tq);

        const float* Kb = Kst + (j & 1) * K_SZ;
        const float* Vb = Vst + (j & 1) * V_SZ;

        // ---- S = Q K^T : 32 rows x 32 keys per warp, K-frags reused x2 ----
        float s[2][4][4];
#pragma unroll
        for (int rt = 0; rt < 2; rt++)
#pragma unroll
            for (int nt = 0; nt < 4; nt++)
#pragma unroll
                for (int c = 0; c < 4; c++) s[rt][nt][c] = 0.f;

#pragma unroll
        for (int ks = 0; ks < 16; ks++) {
            const int k8 = ks * 8;
            unsigned af[2][4];
#pragma unroll
            for (int rt = 0; rt < 2; rt++) {
                const float* Qw = Qs + (wr0 + rt * 16 + gid) * Q_LDS + k8;
                const float* Qw8 = Qw + 8 * Q_LDS;
                af[rt][0] = __float_as_uint(Qw[tq]);
                af[rt][1] = __float_as_uint(Qw8[tq]);
                af[rt][2] = __float_as_uint(Qw[tq + 4]);
                af[rt][3] = __float_as_uint(Qw8[tq + 4]);
            }
#pragma unroll
            for (int nt = 0; nt < 4; nt++) {
                unsigned bf[2];
                bf[0] = __float_as_uint(Kb[(nt * 8 + gid) * K_LDS + k8 + tq]);
                bf[1] = __float_as_uint(Kb[(nt * 8 + gid) * K_LDS + k8 + tq + 4]);
                mma_tf32(s[0][nt], af[0], bf);
                mma_tf32(s[1][nt], af[1], bf);
            }
        }

        // ---- scale + beta*adj ----
#pragma unroll
        for (int rt = 0; rt < 2; rt++)
#pragma unroll
            for (int nt = 0; nt < 4; nt++) {
                s[rt][nt][0] = s[rt][nt][0] * scale + beta * aj[2 * rt][nt].x;
                s[rt][nt][1] = s[rt][nt][1] * scale + beta * aj[2 * rt][nt].y;
                s[rt][nt][2] = s[rt][nt][2] * scale + beta * aj[2 * rt + 1][nt].x;
                s[rt][nt][3] = s[rt][nt][3] * scale + beta * aj[2 * rt + 1][nt].y;
            }

        // ---- online softmax (per row-group) ----
        float fg[4];
#pragma unroll
        for (int rt = 0; rt < 2; rt++) {
            float mx0 = -1e30f, mx1 = -1e30f;
#pragma unroll
            for (int nt = 0; nt < 4; nt++) {
                mx0 = fmaxf(mx0, fmaxf(s[rt][nt][0], s[rt][nt][1]));
                mx1 = fmaxf(mx1, fmaxf(s[rt][nt][2], s[rt][nt][3]));
            }
            mx0 = fmaxf(mx0, __shfl_xor_sync(0xffffffffu, mx0, 1));
            mx0 = fmaxf(mx0, __shfl_xor_sync(0xffffffffu, mx0, 2));
            mx1 = fmaxf(mx1, __shfl_xor_sync(0xffffffffu, mx1, 1));
            mx1 = fmaxf(mx1, __shfl_xor_sync(0xffffffffu, mx1, 2));

            const float mn0 = fmaxf(mR[2 * rt], mx0);
            const float mn1 = fmaxf(mR[2 * rt + 1], mx1);
            fg[2 * rt]     = __expf(mR[2 * rt] - mn0);
            fg[2 * rt + 1] = __expf(mR[2 * rt + 1] - mn1);
            mR[2 * rt] = mn0; mR[2 * rt + 1] = mn1;

            float sum0 = 0.f, sum1 = 0.f;
#pragma unroll
            for (int nt = 0; nt < 4; nt++) {
                s[rt][nt][0] = __expf(s[rt][nt][0] - mn0);
                s[rt][nt][1] = __expf(s[rt][nt][1] - mn0);
                s[rt][nt][2] = __expf(s[rt][nt][2] - mn1);
                s[rt][nt][3] = __expf(s[rt][nt][3] - mn1);
                sum0 += s[rt][nt][0] + s[rt][nt][1];
                sum1 += s[rt][nt][2] + s[rt][nt][3];
            }
            sum0 += __shfl_xor_sync(0xffffffffu, sum0, 1);
            sum0 += __shfl_xor_sync(0xffffffffu, sum0, 2);
            sum1 += __shfl_xor_sync(0xffffffffu, sum1, 1);
            sum1 += __shfl_xor_sync(0xffffffffu, sum1, 2);
            lR[2 * rt]     = lR[2 * rt] * fg[2 * rt] + sum0;
            lR[2 * rt + 1] = lR[2 * rt + 1] * fg[2 * rt + 1] + sum1;
        }

#pragma unroll
        for (int rt = 0; rt < 2; rt++)
#pragma unroll
            for (int nt = 0; nt < 16; nt++) {
                o[rt][nt][0] *= fg[2 * rt];     o[rt][nt][1] *= fg[2 * rt];
                o[rt][nt][2] *= fg[2 * rt + 1]; o[rt][nt][3] *= fg[2 * rt + 1];
            }

        // ---- O += P @ V : P-frags via shuffles, V-frags reused x2 ----
        const int src0 = (lane & 28) | (tq >> 1);
        const int src1 = src0 + 2;
        const bool odd = (tq & 1);
#pragma unroll
        for (int kt = 0; kt < 4; kt++) {
            unsigned pf[2][4];
#pragma unroll
            for (int rt = 0; rt < 2; rt++) {
                float e0 = __shfl_sync(0xffffffffu, s[rt][kt][0], src0);
                float e1 = __shfl_sync(0xffffffffu, s[rt][kt][1], src0);
                float e2 = __shfl_sync(0xffffffffu, s[rt][kt][2], src0);
                float e3 = __shfl_sync(0xffffffffu, s[rt][kt][3], src0);
                float g0 = __shfl_sync(0xffffffffu, s[rt][kt][0], src1);
                float g1 = __shfl_sync(0xffffffffu, s[rt][kt][1], src1);
                float g2 = __shfl_sync(0xffffffffu, s[rt][kt][2], src1);
                float g3 = __shfl_sync(0xffffffffu, s[rt][kt][3], src1);
                pf[rt][0] = f2tf(odd ? e1 : e0);
                pf[rt][1] = f2tf(odd ? e3 : e2);
                pf[rt][2] = f2tf(odd ? g1 : g0);
                pf[rt][3] = f2tf(odd ? g3 : g2);
            }
            const int k8 = kt * 8;
#pragma unroll
            for (int nt = 0; nt < 16; nt++) {
                unsigned bf[2];
                bf[0] = __float_as_uint(Vb[(k8 + tq) * V_LDS + nt * 8 + gid]);
                bf[1] = __float_as_uint(Vb[(k8 + tq + 4) * V_LDS + nt * 8 + gid]);
                mma_tf32(o[0][nt], pf[0], bf);
                mma_tf32(o[1][nt], pf[1], bf);
            }
        }
        __syncthreads();
    }

    // ---- normalize, round to tf32 (consumed as GEMM A-operand), write ----
    float inv[4];
#pragma unroll
    for (int g = 0; g < 4; g++) inv[g] = 1.0f / lR[g];

#pragma unroll
    for (int rt = 0; rt < 2; rt++) {
        float* o0 = AO + (size_t)(q0 + wr0 + rt * 16 + gid) * DD_ + h * DH_;
        float* o1 = o0 + (size_t)8 * DD_;
#pragma unroll
        for (int nt = 0; nt < 16; nt++) {
            const int c = nt * 8 + 2 * tq;
            float a0 = __uint_as_float(f2tf(o[rt][nt][0] * inv[2 * rt]));
            float a1 = __uint_as_float(f2tf(o[rt][nt][1] * inv[2 * rt]));
            float a2 = __uint_as_float(f2tf(o[rt][nt][2] * inv[2 * rt + 1]));
            float a3 = __uint_as_float(f2tf(o[rt][nt][3] * inv[2 * rt + 1]));
            *(float2*)(o0 + c) = make_float2(a0, a1);
            *(float2*)(o1 + c) = make_float2(a2, a3);
        }
    }
}

// ---------------------------------------------------------------------------
// Row LayerNorm over D=1024: out = LN(X + R) * g + b   (R optional)
// ---------------------------------------------------------------------------
template <bool TFOUT>
__global__ void __launch_bounds__(256) ln_row(
    const float* __restrict__ X, const float* __restrict__ R,
    const float* __restrict__ g, const float* __restrict__ b,
    float* __restrict__ out)
{
    __shared__ float red[256];
    const int tid = threadIdx.x;
    const size_t row = blockIdx.x;

    float4 v = ((const float4*)(X + row * DD_))[tid];
    if (R) {
        float4 r = ((const float4*)(R + row * DD_))[tid];
        v.x += r.x; v.y += r.y; v.z += r.z; v.w += r.w;
    }
    red[tid] = v.x + v.y + v.z + v.w;
    __syncthreads();
    for (int s = 128; s > 0; s >>= 1) {
        if (tid < s) red[tid] += red[tid + s];
        __syncthreads();
    }
    const float mu = red[0] * (1.0f / DD_);
    __syncthreads();

    float dx = v.x - mu, dy = v.y - mu, dz = v.z - mu, dw = v.w - mu;
    red[tid] = dx * dx + dy * dy + dz * dz + dw * dw;
    __syncthreads();
    for (int s = 128; s > 0; s >>= 1) {
        if (tid < s) red[tid] += red[tid + s];
        __syncthreads();
    }
    const float rs = rsqrtf(red[0] * (1.0f / DD_) + 1e-5f);

    float4 gg = ((const float4*)g)[tid];
    float4 bb = ((const float4*)b)[tid];
    float4 o;
    o.x = dx * rs * gg.x + bb.x;
    o.y = dy * rs * gg.y + bb.y;
    o.z = dz * rs * gg.z + bb.z;
    o.w = dw * rs * gg.w + bb.w;
    if (TFOUT) {
        o.x = __uint_as_float(f2tf(o.x));
        o.y = __uint_as_float(f2tf(o.y));
        o.z = __uint_as_float(f2tf(o.z));
        o.w = __uint_as_float(f2tf(o.w));
    }
    ((float4*)(out + row * DD_))[tid] = o;
}

// ---------------------------------------------------------------------------
extern "C" void kernel_launch(void* const* d_in, const int* in_sizes, int n_in,
                              void* d_out, int out_size)
{
    const float* x        = (const float*)d_in[0];
    const float* adj      = (const float*)d_in[1];
    const float* Wq       = (const float*)d_in[2];
    const float* Wk       = (const float*)d_in[3];
    const float* Wv       = (const float*)d_in[4];
    const float* Wo_w     = (const float*)d_in[5];
    const float* Wo_b     = (const float*)d_in[6];
    const float* adj_bias = (const float*)d_in[7];
    const float* ln1_g    = (const float*)d_in[8];
    const float* ln1_b    = (const float*)d_in[9];
    const float* ffn_ln_g = (const float*)d_in[10];
    const float* ffn_ln_b = (const float*)d_in[11];
    const float* ffn_w1   = (const float*)d_in[12];
    const float* ffn_b1   = (const float*)d_in[13];
    const float* ffn_w2   = (const float*)d_in[14];
    const float* ffn_b2   = (const float*)d_in[15];
    float* out = (float*)d_out;

    float* scr = nullptr;
    cudaGetSymbolAddress((void**)&scr, g_scratch);

    float* QKV  = scr;                          // 4096 x 3072
    float* AO   = scr + 3 * SZ_ND;
    float* P    = scr + 4 * SZ_ND;
    float* Hb   = scr + 5 * SZ_ND;
    float* Fb   = scr + 6 * SZ_ND;
    float* T    = scr + 7 * SZ_ND;              // 4096 x 2048
    float* x_tf = scr + 9 * SZ_ND;
    float* W3_tf = scr + 10 * SZ_ND;            // 1024 x 3072
    float* Wo_tf = W3_tf + (size_t)DD_ * D3_;
    float* W1_tf = Wo_tf + (size_t)DD_ * DD_;
    float* W2_tf = W1_tf + (size_t)DD_ * FF_;

    const float scale = 0.08838834764831845f;  // 128^-0.5

    const int GEMM_SMEM  = (2 * A_SZ + 2 * B_SZ) * 4;                  // 71,680 B
    const int FLASH_SMEM = (Q_SZ + 2 * K_SZ + 2 * V_SZ) * 4;           // 203,776 B
    static int attr_set = 0;
    if (!attr_set) {
        cudaFuncSetAttribute(gemm_tc<0, true>,  cudaFuncAttributeMaxDynamicSharedMemorySize, GEMM_SMEM);
        cudaFuncSetAttribute(gemm_tc<1, false>, cudaFuncAttributeMaxDynamicSharedMemorySize, GEMM_SMEM);
        cudaFuncSetAttribute(gemm_tc<2, true>,  cudaFuncAttributeMaxDynamicSharedMemorySize, GEMM_SMEM);
        cudaFuncSetAttribute(gemm_tc<3, false>, cudaFuncAttributeMaxDynamicSharedMemorySize, GEMM_SMEM);
        cudaFuncSetAttribute(flash_attn, cudaFuncAttributeMaxDynamicSharedMemorySize, FLASH_SMEM);
        attr_set = 1;
    }

    const int W1M4 = DD_ * DD_ / 4;
    // --- Pre-round x; pack Wq|Wk|Wv into W3_tf; round other weights
    round_tf_k<<<(int)(SZ_ND / 4 + 255) / 256, 256>>>(x, x_tf, (int)(SZ_ND / 4));
    round_tf_cat_k<<<(W1M4 + 255) / 256, 256>>>(Wq, W3_tf, DD_ / 4, D3_ / 4, 0,           W1M4);
    round_tf_cat_k<<<(W1M4 + 255) / 256, 256>>>(Wk, W3_tf, DD_ / 4, D3_ / 4, DD_ / 4,     W1M4);
    round_tf_cat_k<<<(W1M4 + 255) / 256, 256>>>(Wv, W3_tf, DD_ / 4, D3_ / 4, 2 * DD_ / 4, W1M4);
    round_tf_k<<<(W1M4 + 255) / 256, 256>>>(Wo_w, Wo_tf, W1M4);
    round_tf_k<<<(DD_ * FF_ / 4 + 255) / 256, 256>>>(ffn_w1, W1_tf, DD_ * FF_ / 4);
    round_tf_k<<<(FF_ * DD_ / 4 + 255) / 256, 256>>>(ffn_w2, W2_tf, FF_ * DD_ / 4);

    // --- Fused QKV projection: (4096x1024) @ (1024x3072), tf32-rounded out
    dim3 gqkv(D3_ / BN, NN_ / BM);
    gemm_tc<0, true><<<gqkv, GTH, GEMM_SMEM>>>(x_tf, W3_tf, QKV, DD_, DD_, D3_, D3_,
                                               nullptr, nullptr, 0);

    // --- Fused attention; Q/K/V in packed QKV buffer (row stride 3072)
    flash_attn<<<dim3(HH_, NN_ / QROWS), FTH, FLASH_SMEM>>>(
        QKV, QKV + DD_, QKV + 2 * DD_, D3_, adj, adj_bias, AO, scale);

    // --- Output projection with bias (fp32 out)
    dim3 gp(DD_ / BN, NN_ / BM);
    gemm_tc<1, false><<<gp, GTH, GEMM_SMEM>>>(AO, Wo_tf, P, DD_, DD_, DD_, DD_, Wo_b, nullptr, 0);

    // --- h = LN(x + P) fp32;  f = LN(h) tf32-rounded
    ln_row<false><<<NN_, 256>>>(x, P, ln1_g, ln1_b, Hb);
    ln_row<true><<<NN_, 256>>>(Hb, nullptr, ffn_ln_g, ffn_ln_b, Fb);

    // --- FFN1 with fused exact GELU (output tf32-rounded for FFN2)
    dim3 gf1(FF_ / BN, NN_ / BM);
    gemm_tc<2, true><<<gf1, GTH, GEMM_SMEM>>>(Fb, W1_tf, T, DD_, DD_, FF_, FF_, ffn_b1, nullptr, 0);

    // --- FFN2 + bias + residual h (fp32 out)
    dim3 gf2(DD_ / BN, NN_ / BM);
    gemm_tc<3, false><<<gf2, GTH, GEMM_SMEM>>>(T, W2_tf, out, FF_, FF_, DD_, DD_, ffn_b2, Hb, DD_);
}